// round 1
// baseline (speedup 1.0000x reference)
#include <cuda_runtime.h>

#define Bq 4
#define Nq 2048
#define FIN 128
#define Hq 4
#define HIDq 32
#define Eq 4
#define TI 64
#define TJ 32
#define ICH 8

// Scratch (device globals: no allocations allowed)
__device__ float g_ht[Bq*Hq*Nq*HIDq];   // [b][h][n][d]  (after k3: ht/l)
__device__ float g_si[Bq*Hq*Nq];        // [b][h][n]
__device__ float g_lp[ICH*Bq*Hq*Nq];    // partial column sums

// ---------------- k1: ht = h @ W (per-row), s_i = <ht, a_i> ----------------
__global__ void k1_proj(const float* __restrict__ hin,
                        const float* __restrict__ W,
                        const float* __restrict__ a) {
    int bn = blockIdx.x;
    int b = bn >> 11, n = bn & (Nq - 1);
    __shared__ float sh[FIN];
    int t = threadIdx.x;
    sh[t] = hin[bn * FIN + t];
    __syncthreads();
    float acc = 0.f;
#pragma unroll 16
    for (int k = 0; k < FIN; k++) acc += sh[k] * W[(k << 7) + t];
    int hh = t >> 5, d = t & 31;
    g_ht[(((b * Hq + hh) * Nq) + n) * HIDq + d] = acc;
    // s_i reduction within the head's warp (lanes = d)
    float v = acc * a[hh * 68 + d];     // a: [H][2*HID+E], a_i = a[h][0:32]
#pragma unroll
    for (int o = 16; o > 0; o >>= 1) v += __shfl_xor_sync(0xffffffffu, v, o);
    if (d == 0) g_si[(b * Hq + hh) * Nq + n] = v;
}

// ---------------- k2: partial column sums l[b,h,j] over i-chunks ----------------
__global__ void k2_colsum(const int* __restrict__ adj,
                          const float4* __restrict__ edge,
                          const float* __restrict__ a) {
    int ic = blockIdx.x, jt = blockIdx.y, b = blockIdx.z;
    int j = jt * 256 + threadIdx.x;
    int i0 = ic * 256;
    __shared__ float ssi[Hq][256];
    for (int q = threadIdx.x; q < Hq * 256; q += 256) {
        int hh = q >> 8, il = q & 255;
        ssi[hh][il] = g_si[(b * Hq + hh) * Nq + i0 + il];
    }
    float ae[4][4];
#pragma unroll
    for (int hh = 0; hh < 4; hh++)
#pragma unroll
        for (int e = 0; e < 4; e++) ae[hh][e] = a[hh * 68 + 2 * HIDq + e];
    __syncthreads();

    float acc0 = 0.f, acc1 = 0.f, acc2 = 0.f, acc3 = 0.f;
    const int*    adjp = adj  + (size_t)(b * Nq + i0) * Nq + j;
    const float4* ep   = edge + (size_t)(b * Nq + i0) * Nq + j;
    for (int ii = 0; ii < 256; ii++) {
        int ad = adjp[(size_t)ii * Nq];
        float4 e4 = ep[(size_t)ii * Nq];
        float v0 = ssi[0][ii] + e4.x*ae[0][0] + e4.y*ae[0][1] + e4.z*ae[0][2] + e4.w*ae[0][3];
        float v1 = ssi[1][ii] + e4.x*ae[1][0] + e4.y*ae[1][1] + e4.z*ae[1][2] + e4.w*ae[1][3];
        float v2 = ssi[2][ii] + e4.x*ae[2][0] + e4.y*ae[2][1] + e4.z*ae[2][2] + e4.w*ae[2][3];
        float v3 = ssi[3][ii] + e4.x*ae[3][0] + e4.y*ae[3][1] + e4.z*ae[3][2] + e4.w*ae[3][3];
        if (ad > 0) {
            acc0 += __expf(v0); acc1 += __expf(v1);
            acc2 += __expf(v2); acc3 += __expf(v3);
        }
    }
    int base = (ic * Bq * Hq + b * Hq) * Nq + j;
    g_lp[base + 0 * Nq] = acc0;
    g_lp[base + 1 * Nq] = acc1;
    g_lp[base + 2 * Nq] = acc2;
    g_lp[base + 3 * Nq] = acc3;
}

// ---------------- k3: fold 1/l into ht ----------------
__global__ void k3_scale() {
    int bh = blockIdx.y;
    int j0 = blockIdx.x * 256;
    int t = threadIdx.x;
    __shared__ float sinv[256];
    float l = 0.f;
#pragma unroll
    for (int ic = 0; ic < ICH; ic++) l += g_lp[(ic * Bq * Hq + bh) * Nq + j0 + t];
    sinv[t] = (l > 0.f) ? 1.f / l : 0.f;
    __syncthreads();
    float* hp = g_ht + ((size_t)bh * Nq + j0) * HIDq;
    for (int q = t; q < 256 * HIDq; q += 256) hp[q] *= sinv[q >> 5];
}

// ---------------- k4: recompute w tile-wise (shared by 4 heads), GEMM out ----------------
__global__ __launch_bounds__(128, 1)
void k4_agg(const int* __restrict__ adj,
            const float4* __restrict__ edge,
            const float* __restrict__ a,
            float* __restrict__ out) {
    int b  = blockIdx.y;
    int i0 = blockIdx.x * TI;
    int t  = threadIdx.x;

    __shared__ float sA[Hq][TJ][TI + 4];   // w[h][jj][i], pad 68 (16B-aligned rows)
    __shared__ float sB[Hq][TJ][HIDq];     // htp[h][jj][d]
    __shared__ float ssi[Hq][TI];

    for (int q = t; q < Hq * TI; q += 128) {
        int hh = q >> 6, il = q & 63;
        ssi[hh][il] = g_si[(b * Hq + hh) * Nq + i0 + il];
    }
    float ae[4][4];
#pragma unroll
    for (int hh = 0; hh < 4; hh++)
#pragma unroll
        for (int e = 0; e < 4; e++) ae[hh][e] = a[hh * 68 + 2 * HIDq + e];

    int wjj = t & 31, wib = t >> 5;    // staging map (lanes -> consecutive j)
    int h    = t >> 5;                 // GEMM: warp == head
    int lane = t & 31;
    int ig = lane & 7, dg = lane >> 3; // 8x8 micro-tile per thread

    float acc[8][8];
#pragma unroll
    for (int x = 0; x < 8; x++)
#pragma unroll
        for (int y = 0; y < 8; y++) acc[x][y] = 0.f;

    __syncthreads();

    for (int jc = 0; jc < Nq / TJ; jc++) {
        int j0 = jc * TJ;
        // stage htp tile -> sB (coalesced over d)
        for (int q = t; q < Hq * TJ * HIDq; q += 128) {
            int hh = q >> 10;
            int jj = (q >> 5) & 31;
            int d  = q & 31;
            sB[hh][jj][d] = g_ht[(((b * Hq + hh) * Nq) + j0 + jj) * HIDq + d];
        }
        // stage w tile -> sA (adj/edge read ONCE for all 4 heads)
#pragma unroll 4
        for (int r = 0; r < 16; r++) {
            int il = r * 4 + wib;
            int i  = i0 + il;
            int ad = adj[(size_t)(b * Nq + i) * Nq + j0 + wjj];
            float4 e4 = edge[(size_t)(b * Nq + i) * Nq + j0 + wjj];
#pragma unroll
            for (int hh = 0; hh < 4; hh++) {
                float v = ssi[hh][il] + e4.x*ae[hh][0] + e4.y*ae[hh][1]
                                       + e4.z*ae[hh][2] + e4.w*ae[hh][3];
                sA[hh][wjj][il] = (ad > 0) ? __expf(v) : 0.f;
            }
        }
        __syncthreads();
        // per-head 64x32 GEMM, K = 32
#pragma unroll 8
        for (int jj = 0; jj < TJ; jj++) {
            float4 a0 = *reinterpret_cast<const float4*>(&sA[h][jj][ig * 8]);
            float4 a1 = *reinterpret_cast<const float4*>(&sA[h][jj][ig * 8 + 4]);
            float4 b0 = *reinterpret_cast<const float4*>(&sB[h][jj][dg * 8]);
            float4 b1 = *reinterpret_cast<const float4*>(&sB[h][jj][dg * 8 + 4]);
            float av[8] = {a0.x,a0.y,a0.z,a0.w,a1.x,a1.y,a1.z,a1.w};
            float bv[8] = {b0.x,b0.y,b0.z,b0.w,b1.x,b1.y,b1.z,b1.w};
#pragma unroll
            for (int x = 0; x < 8; x++)
#pragma unroll
                for (int y = 0; y < 8; y++) acc[x][y] += av[x] * bv[y];
        }
        __syncthreads();
    }

    // epilogue: out[b][i][h*32 + d]
#pragma unroll
    for (int x = 0; x < 8; x++) {
        int i = i0 + ig * 8 + x;
        float* op = out + ((size_t)(b * Nq + i)) * (Hq * HIDq) + h * HIDq + dg * 8;
        float4 o0 = {acc[x][0], acc[x][1], acc[x][2], acc[x][3]};
        float4 o1 = {acc[x][4], acc[x][5], acc[x][6], acc[x][7]};
        *reinterpret_cast<float4*>(op)     = o0;
        *reinterpret_cast<float4*>(op + 4) = o1;
    }
}

extern "C" void kernel_launch(void* const* d_in, const int* in_sizes, int n_in,
                              void* d_out, int out_size) {
    const float* hin  = (const float*)d_in[0];
    const int*   adj  = (const int*)  d_in[1];
    const float* edge = (const float*)d_in[2];
    const float* W    = (const float*)d_in[3];
    const float* a    = (const float*)d_in[4];
    float* out = (float*)d_out;

    k1_proj<<<Bq * Nq, 128>>>(hin, W, a);
    k2_colsum<<<dim3(ICH, Nq / 256, Bq), 256>>>(adj, (const float4*)edge, a);
    k3_scale<<<dim3(Nq / 256, Bq * Hq), 256>>>();
    k4_agg<<<dim3(Nq / TI, Bq), 128>>>(adj, (const float4*)edge, a, out);
}

// round 2
// speedup vs baseline: 1.8755x; 1.8755x over previous
#include <cuda_runtime.h>

#define Bq 4
#define Nq 2048
#define FIN 128
#define Hq 4
#define HIDq 32
#define Eq 4
#define TI 64
#define TJ 32
#define ICH 8
#define JS 8          // j-splits for k4 (grid parallelism)

// Scratch (device globals: no allocations allowed)
__device__ float g_ht[Bq*Hq*Nq*HIDq];          // [b][h][n][d]  (after k3: ht/l)
__device__ float g_si[Bq*Hq*Nq];               // [b][h][n]
__device__ float g_lp[ICH*Bq*Hq*Nq];           // partial column sums
__device__ float g_po[JS*Bq*Nq*Hq*HIDq];       // k4 partial outputs [jz][b][i][h*32+d]

// ---------------- k1: ht = h @ W (per-row), s_i = <ht, a_i> ----------------
__global__ void k1_proj(const float* __restrict__ hin,
                        const float* __restrict__ W,
                        const float* __restrict__ a) {
    int bn = blockIdx.x;
    int b = bn >> 11, n = bn & (Nq - 1);
    __shared__ float sh[FIN];
    int t = threadIdx.x;
    sh[t] = hin[bn * FIN + t];
    __syncthreads();
    float acc = 0.f;
#pragma unroll 16
    for (int k = 0; k < FIN; k++) acc += sh[k] * W[(k << 7) + t];
    int hh = t >> 5, d = t & 31;
    g_ht[(((b * Hq + hh) * Nq) + n) * HIDq + d] = acc;
    float v = acc * a[hh * 68 + d];     // a: [H][2*HID+E], a_i = a[h][0:32]
#pragma unroll
    for (int o = 16; o > 0; o >>= 1) v += __shfl_xor_sync(0xffffffffu, v, o);
    if (d == 0) g_si[(b * Hq + hh) * Nq + n] = v;
}

// ---------------- k2: partial column sums l[b,h,j] over i-chunks ----------------
__global__ void k2_colsum(const int* __restrict__ adj,
                          const float4* __restrict__ edge,
                          const float* __restrict__ a) {
    int ic = blockIdx.x, jt = blockIdx.y, b = blockIdx.z;
    int j = jt * 256 + threadIdx.x;
    int i0 = ic * 256;
    __shared__ float ssi[Hq][256];
    for (int q = threadIdx.x; q < Hq * 256; q += 256) {
        int hh = q >> 8, il = q & 255;
        ssi[hh][il] = g_si[(b * Hq + hh) * Nq + i0 + il];
    }
    float ae[4][4];
#pragma unroll
    for (int hh = 0; hh < 4; hh++)
#pragma unroll
        for (int e = 0; e < 4; e++) ae[hh][e] = a[hh * 68 + 2 * HIDq + e];
    __syncthreads();

    float acc0 = 0.f, acc1 = 0.f, acc2 = 0.f, acc3 = 0.f;
    const int*    adjp = adj  + (size_t)(b * Nq + i0) * Nq + j;
    const float4* ep   = edge + (size_t)(b * Nq + i0) * Nq + j;
    for (int ii = 0; ii < 256; ii++) {
        int ad = adjp[(size_t)ii * Nq];
        float4 e4 = ep[(size_t)ii * Nq];
        float v0 = ssi[0][ii] + e4.x*ae[0][0] + e4.y*ae[0][1] + e4.z*ae[0][2] + e4.w*ae[0][3];
        float v1 = ssi[1][ii] + e4.x*ae[1][0] + e4.y*ae[1][1] + e4.z*ae[1][2] + e4.w*ae[1][3];
        float v2 = ssi[2][ii] + e4.x*ae[2][0] + e4.y*ae[2][1] + e4.z*ae[2][2] + e4.w*ae[2][3];
        float v3 = ssi[3][ii] + e4.x*ae[3][0] + e4.y*ae[3][1] + e4.z*ae[3][2] + e4.w*ae[3][3];
        if (ad > 0) {
            acc0 += __expf(v0); acc1 += __expf(v1);
            acc2 += __expf(v2); acc3 += __expf(v3);
        }
    }
    int base = (ic * Bq * Hq + b * Hq) * Nq + j;
    g_lp[base + 0 * Nq] = acc0;
    g_lp[base + 1 * Nq] = acc1;
    g_lp[base + 2 * Nq] = acc2;
    g_lp[base + 3 * Nq] = acc3;
}

// ---------------- k3: fold 1/l into ht ----------------
__global__ void k3_scale() {
    int bh = blockIdx.y;
    int j0 = blockIdx.x * 256;
    int t = threadIdx.x;
    __shared__ float sinv[256];
    float l = 0.f;
#pragma unroll
    for (int ic = 0; ic < ICH; ic++) l += g_lp[(ic * Bq * Hq + bh) * Nq + j0 + t];
    sinv[t] = (l > 0.f) ? 1.f / l : 0.f;
    __syncthreads();
    float* hp = g_ht + ((size_t)bh * Nq + j0) * HIDq;
    for (int q = t; q < 256 * HIDq; q += 256) hp[q] *= sinv[q >> 5];
}

// ---------------- k4: recompute w tile-wise (shared by 4 heads), GEMM partials ----------------
__global__ __launch_bounds__(128, 3)
void k4_agg(const int* __restrict__ adj,
            const float4* __restrict__ edge,
            const float* __restrict__ a) {
    int b  = blockIdx.y;
    int i0 = blockIdx.x * TI;
    int jz = blockIdx.z;
    int t  = threadIdx.x;

    __shared__ float sA[Hq][TJ][TI + 4];   // w[h][jj][i]
    __shared__ float sB[Hq][TJ][HIDq];     // htp[h][jj][d]
    __shared__ float ssi[Hq][TI];

    for (int q = t; q < Hq * TI; q += 128) {
        int hh = q >> 6, il = q & 63;
        ssi[hh][il] = g_si[(b * Hq + hh) * Nq + i0 + il];
    }
    float ae[4][4];
#pragma unroll
    for (int hh = 0; hh < 4; hh++)
#pragma unroll
        for (int e = 0; e < 4; e++) ae[hh][e] = a[hh * 68 + 2 * HIDq + e];

    int wjj = t & 31, wib = t >> 5;    // staging map (lanes -> consecutive j)
    int h    = t >> 5;                 // GEMM: warp == head
    int lane = t & 31;
    int ig = lane & 7, dg = lane >> 3; // 8x8 micro-tile per thread

    float acc[8][8];
#pragma unroll
    for (int x = 0; x < 8; x++)
#pragma unroll
        for (int y = 0; y < 8; y++) acc[x][y] = 0.f;

    __syncthreads();

    int jc0 = jz * (Nq / TJ / JS);
    int jc1 = jc0 + (Nq / TJ / JS);
    for (int jc = jc0; jc < jc1; jc++) {
        int j0 = jc * TJ;
        // stage htp tile -> sB (coalesced over d)
        for (int q = t; q < Hq * TJ * HIDq; q += 128) {
            int hh = q >> 10;
            int jj = (q >> 5) & 31;
            int d  = q & 31;
            sB[hh][jj][d] = g_ht[(((b * Hq + hh) * Nq) + j0 + jj) * HIDq + d];
        }
        // stage w tile -> sA (adj/edge read ONCE for all 4 heads)
#pragma unroll 4
        for (int r = 0; r < 16; r++) {
            int il = r * 4 + wib;
            int i  = i0 + il;
            int ad = adj[(size_t)(b * Nq + i) * Nq + j0 + wjj];
            float4 e4 = edge[(size_t)(b * Nq + i) * Nq + j0 + wjj];
#pragma unroll
            for (int hh = 0; hh < 4; hh++) {
                float v = ssi[hh][il] + e4.x*ae[hh][0] + e4.y*ae[hh][1]
                                       + e4.z*ae[hh][2] + e4.w*ae[hh][3];
                sA[hh][wjj][il] = (ad > 0) ? __expf(v) : 0.f;
            }
        }
        __syncthreads();
        // per-head 64x32 GEMM, K = 32
#pragma unroll 8
        for (int jj = 0; jj < TJ; jj++) {
            float4 a0 = *reinterpret_cast<const float4*>(&sA[h][jj][ig * 8]);
            float4 a1 = *reinterpret_cast<const float4*>(&sA[h][jj][ig * 8 + 4]);
            float4 b0 = *reinterpret_cast<const float4*>(&sB[h][jj][dg * 8]);
            float4 b1 = *reinterpret_cast<const float4*>(&sB[h][jj][dg * 8 + 4]);
            float av[8] = {a0.x,a0.y,a0.z,a0.w,a1.x,a1.y,a1.z,a1.w};
            float bv[8] = {b0.x,b0.y,b0.z,b0.w,b1.x,b1.y,b1.z,b1.w};
#pragma unroll
            for (int x = 0; x < 8; x++)
#pragma unroll
                for (int y = 0; y < 8; y++) acc[x][y] += av[x] * bv[y];
        }
        __syncthreads();
    }

    // epilogue: partial out [jz][b][i][h*32 + d]
    float* po = g_po + (size_t)jz * (Bq * Nq * Hq * HIDq);
#pragma unroll
    for (int x = 0; x < 8; x++) {
        int i = i0 + ig * 8 + x;
        float* op = po + ((size_t)(b * Nq + i)) * (Hq * HIDq) + h * HIDq + dg * 8;
        float4 o0 = {acc[x][0], acc[x][1], acc[x][2], acc[x][3]};
        float4 o1 = {acc[x][4], acc[x][5], acc[x][6], acc[x][7]};
        *reinterpret_cast<float4*>(op)     = o0;
        *reinterpret_cast<float4*>(op + 4) = o1;
    }
}

// ---------------- k5: reduce partials -> out ----------------
__global__ void k5_reduce(float4* __restrict__ out) {
    int idx = blockIdx.x * 256 + threadIdx.x;   // float4 index
    const float4* po = (const float4*)g_po;
    const int stride = Bq * Nq * Hq * HIDq / 4;
    float4 s = po[idx];
#pragma unroll
    for (int jz = 1; jz < JS; jz++) {
        float4 v = po[(size_t)jz * stride + idx];
        s.x += v.x; s.y += v.y; s.z += v.z; s.w += v.w;
    }
    out[idx] = s;
}

extern "C" void kernel_launch(void* const* d_in, const int* in_sizes, int n_in,
                              void* d_out, int out_size) {
    const float* hin  = (const float*)d_in[0];
    const int*   adj  = (const int*)  d_in[1];
    const float* edge = (const float*)d_in[2];
    const float* W    = (const float*)d_in[3];
    const float* a    = (const float*)d_in[4];
    float* out = (float*)d_out;

    k1_proj<<<Bq * Nq, 128>>>(hin, W, a);
    k2_colsum<<<dim3(ICH, Nq / 256, Bq), 256>>>(adj, (const float4*)edge, a);
    k3_scale<<<dim3(Nq / 256, Bq * Hq), 256>>>();
    k4_agg<<<dim3(Nq / TI, Bq, JS), 128>>>(adj, (const float4*)edge, a);
    k5_reduce<<<(Bq * Nq * Hq * HIDq / 4) / 256, 256>>>((float4*)out);
}

// round 3
// speedup vs baseline: 3.4863x; 1.8589x over previous
#include <cuda_runtime.h>
#include <cstdint>

#define Bq 4
#define Nq 2048
#define FIN 128
#define Hq 4
#define HIDq 32
#define Eq 4
#define TI 64
#define TJ 32
#define NIC 32         // i-chunks in k2 (Nq/64)
#define JS 4           // j-splits for k4

// Scratch (device globals: no allocations allowed)
__device__ float g_ht[Bq*Hq*Nq*HIDq];            // [b][h][n][d]  (after k3: ht/l)
__device__ float g_si[Bq*Hq*Nq];                 // [b][h][n]
__device__ float g_lp[NIC*Bq*Hq*Nq];             // partial column sums [ic][b][h][j]
__device__ float g_w[(size_t)Bq*Hq*Nq*Nq];       // attention weights (unnormalized) [b][h][i][j]
__device__ float g_po[(size_t)JS*Bq*Nq*Hq*HIDq]; // k4 partial outputs [jz][b][i][h*32+d]

// ---------------- k1: ht = h @ W (per-row), s_i = <ht, a_i> ----------------
__global__ void k1_proj(const float* __restrict__ hin,
                        const float* __restrict__ W,
                        const float* __restrict__ a) {
    int bn = blockIdx.x;
    int b = bn >> 11, n = bn & (Nq - 1);
    __shared__ float sh[FIN];
    int t = threadIdx.x;
    sh[t] = hin[bn * FIN + t];
    __syncthreads();
    float acc = 0.f;
#pragma unroll 16
    for (int k = 0; k < FIN; k++) acc += sh[k] * W[(k << 7) + t];
    int hh = t >> 5, d = t & 31;
    g_ht[(((b * Hq + hh) * Nq) + n) * HIDq + d] = acc;
    float v = acc * a[hh * 68 + d];     // a: [H][2*HID+E], a_i = a[h][0:32]
#pragma unroll
    for (int o = 16; o > 0; o >>= 1) v += __shfl_xor_sync(0xffffffffu, v, o);
    if (d == 0) g_si[(b * Hq + hh) * Nq + n] = v;
}

// ------- k2: compute w = mask * exp(s_i + s_e), write w, partial column sums -------
__global__ __launch_bounds__(256)
void k2_w(const int* __restrict__ adj,
          const float4* __restrict__ edge,
          const float* __restrict__ a) {
    int t  = threadIdx.x;
    int j  = blockIdx.y * 256 + t;
    int b  = blockIdx.z;
    int ic = blockIdx.x;
    int i0 = ic * 64;

    __shared__ float ssi[Hq][64];
    {
        int hh = t >> 6, il = t & 63;   // 256 threads cover 4*64
        ssi[hh][il] = g_si[(b * Hq + hh) * Nq + i0 + il];
    }
    float ae[4][4];
#pragma unroll
    for (int hh = 0; hh < 4; hh++)
#pragma unroll
        for (int e = 0; e < 4; e++) ae[hh][e] = a[hh * 68 + 2 * HIDq + e];
    __syncthreads();

    float acc0 = 0.f, acc1 = 0.f, acc2 = 0.f, acc3 = 0.f;
    const int*    adjp = adj  + (size_t)(b * Nq + i0) * Nq + j;
    const float4* ep   = edge + (size_t)(b * Nq + i0) * Nq + j;
    float* wp = g_w + (size_t)(b * Hq * Nq + i0) * Nq + j;   // [b][h=0][i0][j]
    const size_t hstride = (size_t)Nq * Nq;

#pragma unroll 4
    for (int ii = 0; ii < 64; ii++) {
        int ad = adjp[(size_t)ii * Nq];
        float4 e4 = ep[(size_t)ii * Nq];
        float v0 = ssi[0][ii] + e4.x*ae[0][0] + e4.y*ae[0][1] + e4.z*ae[0][2] + e4.w*ae[0][3];
        float v1 = ssi[1][ii] + e4.x*ae[1][0] + e4.y*ae[1][1] + e4.z*ae[1][2] + e4.w*ae[1][3];
        float v2 = ssi[2][ii] + e4.x*ae[2][0] + e4.y*ae[2][1] + e4.z*ae[2][2] + e4.w*ae[2][3];
        float v3 = ssi[3][ii] + e4.x*ae[3][0] + e4.y*ae[3][1] + e4.z*ae[3][2] + e4.w*ae[3][3];
        float w0 = (ad > 0) ? __expf(v0) : 0.f;
        float w1 = (ad > 0) ? __expf(v1) : 0.f;
        float w2 = (ad > 0) ? __expf(v2) : 0.f;
        float w3 = (ad > 0) ? __expf(v3) : 0.f;
        size_t ro = (size_t)ii * Nq;
        wp[ro]               = w0;
        wp[ro + hstride]     = w1;
        wp[ro + 2*hstride]   = w2;
        wp[ro + 3*hstride]   = w3;
        acc0 += w0; acc1 += w1; acc2 += w2; acc3 += w3;
    }
    int base = ((ic * Bq + b) * Hq) * Nq + j;
    g_lp[base + 0 * Nq] = acc0;
    g_lp[base + 1 * Nq] = acc1;
    g_lp[base + 2 * Nq] = acc2;
    g_lp[base + 3 * Nq] = acc3;
}

// ---------------- k3: fold 1/l into ht ----------------
__global__ void k3_scale() {
    int bh = blockIdx.y;
    int j0 = blockIdx.x * 256;
    int t = threadIdx.x;
    __shared__ float sinv[256];
    int b = bh >> 2, h = bh & 3;
    float l = 0.f;
#pragma unroll
    for (int ic = 0; ic < NIC; ic++) l += g_lp[((ic * Bq + b) * Hq + h) * Nq + j0 + t];
    sinv[t] = (l > 0.f) ? 1.f / l : 0.f;
    __syncthreads();
    float* hp = g_ht + ((size_t)bh * Nq + j0) * HIDq;
    for (int q = t; q < 256 * HIDq; q += 256) hp[q] *= sinv[q >> 5];
}

// ---------------- k4: pure GEMM  po[jz] += w @ htp  (FFMA2, swizzled smem) ----------------
__global__ __launch_bounds__(128, 4)
void k4_gemm() {
    int b  = blockIdx.y;
    int i0 = blockIdx.x * TI;
    int jz = blockIdx.z;
    int t  = threadIdx.x;
    int w  = t >> 5, l = t & 31;

    __shared__ float sA[Hq * TI * TJ];     // [h][il][jj], float4-swizzled: jj4 ^= il&7  (32KB)
    __shared__ float sB[Hq * TJ * HIDq];   // [h][jj][d]                                  (16KB)

    int h  = w;            // GEMM: warp == head
    int ig = l & 7;        // i-lane: rows x*8 + ig
    int dg = l >> 3;       // d-group: cols dg*8 .. dg*8+7

    // staging ids for sA
    int row_sub = l >> 3;  // 0..3
    int jj4     = l & 7;   // float4 column 0..7

    unsigned long long acc[8][4];
#pragma unroll
    for (int x = 0; x < 8; x++)
#pragma unroll
        for (int y = 0; y < 4; y++) acc[x][y] = 0ull;

    const int jc0 = jz * (Nq / TJ / JS);
    const int jc1 = jc0 + (Nq / TJ / JS);

    for (int jc = jc0; jc < jc1; jc++) {
        int j0 = jc * TJ;
        // stage htp tile -> sB (1024 float4, coalesced over d)
#pragma unroll
        for (int q = t; q < Hq * TJ * HIDq / 4; q += 128) {
            int hh = q >> 8;
            int jj = (q >> 3) & 31;
            int d4 = q & 7;
            float4 v = *(const float4*)(g_ht + ((size_t)((b*Hq+hh)*Nq) + j0 + jj) * HIDq + d4*4);
            *(float4*)(sB + (size_t)q * 4) = v;
        }
        // stage w tile -> sA (swizzled, conflict-free)
#pragma unroll 4
        for (int r = 0; r < 16; r++) {
            int row = r * 16 + w * 4 + row_sub;   // 0..255 = (h,il)
            int hh = row >> 6, il = row & 63;
            float4 v = *(const float4*)(g_w + ((size_t)((b*Hq+hh)*Nq) + i0 + il) * Nq + j0 + jj4*4);
            int p4 = jj4 ^ (il & 7);
            *(float4*)(sA + row * TJ + p4 * 4) = v;
        }
        __syncthreads();

        // per-head 64x32 GEMM, K=32, packed f32x2
#pragma unroll 4
        for (int jj = 0; jj < TJ; jj++) {
            const float* bp = sB + (h * TJ + jj) * HIDq + dg * 8;
            ulonglong2 B0 = *(const ulonglong2*)(bp);
            ulonglong2 B1 = *(const ulonglong2*)(bp + 4);
            unsigned long long bb0 = B0.x, bb1 = B0.y, bb2 = B1.x, bb3 = B1.y;
            int p = jj >> 2, c = jj & 3;
            int sw = ((p ^ ig) << 2) + c;      // swizzled scalar offset within row
#pragma unroll
            for (int x = 0; x < 8; x++) {
                int row = x * 8 + ig;          // row & 7 == ig
                float av = sA[(h * TI + row) * TJ + sw];
                unsigned int au = __float_as_uint(av);
                unsigned long long a2;
                asm("mov.b64 %0, {%1, %2};" : "=l"(a2) : "r"(au), "r"(au));
                asm("fma.rn.f32x2 %0, %1, %2, %0;" : "+l"(acc[x][0]) : "l"(a2), "l"(bb0));
                asm("fma.rn.f32x2 %0, %1, %2, %0;" : "+l"(acc[x][1]) : "l"(a2), "l"(bb1));
                asm("fma.rn.f32x2 %0, %1, %2, %0;" : "+l"(acc[x][2]) : "l"(a2), "l"(bb2));
                asm("fma.rn.f32x2 %0, %1, %2, %0;" : "+l"(acc[x][3]) : "l"(a2), "l"(bb3));
            }
        }
        __syncthreads();
    }

    // epilogue: partial out [jz][b][i][h*32 + d]
    float* po = g_po + (size_t)jz * (Bq * Nq * Hq * HIDq);
#pragma unroll
    for (int x = 0; x < 8; x++) {
        int i = i0 + x * 8 + ig;
        float* op = po + ((size_t)(b * Nq + i)) * (Hq * HIDq) + h * HIDq + dg * 8;
        ulonglong2 o0 = {acc[x][0], acc[x][1]};
        ulonglong2 o1 = {acc[x][2], acc[x][3]};
        *(ulonglong2*)op       = o0;
        *(ulonglong2*)(op + 4) = o1;
    }
}

// ---------------- k5: reduce partials -> out ----------------
__global__ void k5_reduce(float4* __restrict__ out) {
    int idx = blockIdx.x * 256 + threadIdx.x;   // float4 index
    const float4* po = (const float4*)g_po;
    const int stride = Bq * Nq * Hq * HIDq / 4;
    float4 s = po[idx];
#pragma unroll
    for (int jz = 1; jz < JS; jz++) {
        float4 v = po[(size_t)jz * stride + idx];
        s.x += v.x; s.y += v.y; s.z += v.z; s.w += v.w;
    }
    out[idx] = s;
}

extern "C" void kernel_launch(void* const* d_in, const int* in_sizes, int n_in,
                              void* d_out, int out_size) {
    const float* hin  = (const float*)d_in[0];
    const int*   adj  = (const int*)  d_in[1];
    const float* edge = (const float*)d_in[2];
    const float* W    = (const float*)d_in[3];
    const float* a    = (const float*)d_in[4];
    float* out = (float*)d_out;

    k1_proj<<<Bq * Nq, 128>>>(hin, W, a);
    k2_w<<<dim3(NIC, Nq / 256, Bq), 256>>>(adj, (const float4*)edge, a);
    k3_scale<<<dim3(Nq / 256, Bq * Hq), 256>>>();
    k4_gemm<<<dim3(Nq / TI, Bq, JS), 128>>>();
    k5_reduce<<<(Bq * Nq * Hq * HIDq / 4) / 256, 256>>>((float4*)out);
}

// round 5
// speedup vs baseline: 4.0897x; 1.1731x over previous
#include <cuda_runtime.h>
#include <cstdint>

#define Bq 4
#define Nq 2048
#define FIN 128
#define Hq 4
#define HIDq 32
#define NIC 32
#define KC 32
#define NCHUNK (Nq/KC)     // 64
#define STAGES 4

#define A_ROWS 128
#define RS 36                       // padded row stride (floats) -> conflict-free frags
#define A_STAGE_F (A_ROWS*RS)       // 4608 floats
#define B_STAGE_F (32*RS)           // 1152 floats
#define STAGE_F   (A_STAGE_F + B_STAGE_F)            // 5760 floats = 23040 B
#define SMEM_DYN  (STAGES * STAGE_F * 4 + 32)

// Scratch (device globals: no allocations allowed)
__device__ float g_ht[Bq*Hq*Nq*HIDq];          // [bh][n][d]
__device__ float g_si[Bq*Hq*Nq];               // [bh][n]
__device__ float g_lp[NIC*Bq*Hq*Nq];           // partial column sums
__device__ float g_w[(size_t)Bq*Hq*Nq*Nq];     // tf32-rounded weights [bh][i][j]
__device__ float g_htT[Bq*Hq*HIDq*Nq];         // tf32-rounded htp^T   [bh][d][j]

__device__ __forceinline__ float tf32r(float x) {
    unsigned r;
    asm("cvt.rna.tf32.f32 %0, %1;" : "=r"(r) : "f"(x));
    return __uint_as_float(r);
}
__device__ __forceinline__ uint32_t s2u(const void* p) {
    uint32_t a;
    asm("{ .reg .u64 t; cvta.to.shared.u64 t, %1; cvt.u32.u64 %0, t; }" : "=r"(a) : "l"(p));
    return a;
}
__device__ __forceinline__ void cpa16(uint32_t dst, const void* src) {
    asm volatile("cp.async.cg.shared.global [%0], [%1], 16;" :: "r"(dst), "l"(src) : "memory");
}

// ---------------- k1: ht = h @ W, s_i = <ht, a_i> ----------------
__global__ void k1_proj(const float* __restrict__ hin,
                        const float* __restrict__ W,
                        const float* __restrict__ a) {
    int bn = blockIdx.x;
    int b = bn >> 11, n = bn & (Nq - 1);
    __shared__ float sh[FIN];
    int t = threadIdx.x;
    sh[t] = hin[bn * FIN + t];
    __syncthreads();
    float acc = 0.f;
#pragma unroll 16
    for (int k = 0; k < FIN; k++) acc += sh[k] * W[(k << 7) + t];
    int hh = t >> 5, d = t & 31;
    g_ht[(((b * Hq + hh) * Nq) + n) * HIDq + d] = acc;
    float v = acc * a[hh * 68 + d];
#pragma unroll
    for (int o = 16; o > 0; o >>= 1) v += __shfl_xor_sync(0xffffffffu, v, o);
    if (d == 0) g_si[(b * Hq + hh) * Nq + n] = v;
}

// ------- k2: w = tf32(mask * exp(s_i + s_e)), partial column sums -------
__global__ __launch_bounds__(256)
void k2_w(const int* __restrict__ adj,
          const float4* __restrict__ edge,
          const float* __restrict__ a) {
    int t  = threadIdx.x;
    int j  = blockIdx.y * 256 + t;
    int b  = blockIdx.z;
    int ic = blockIdx.x;
    int i0 = ic * 64;

    __shared__ float ssi[Hq][64];
    {
        int hh = t >> 6, il = t & 63;
        ssi[hh][il] = g_si[(b * Hq + hh) * Nq + i0 + il];
    }
    float ae[4][4];
#pragma unroll
    for (int hh = 0; hh < 4; hh++)
#pragma unroll
        for (int e = 0; e < 4; e++) ae[hh][e] = a[hh * 68 + 2 * HIDq + e];
    __syncthreads();

    float acc0 = 0.f, acc1 = 0.f, acc2 = 0.f, acc3 = 0.f;
    const int*    adjp = adj  + (size_t)(b * Nq + i0) * Nq + j;
    const float4* ep   = edge + (size_t)(b * Nq + i0) * Nq + j;
    float* wp = g_w + (size_t)(b * Hq * Nq + i0) * Nq + j;
    const size_t hstride = (size_t)Nq * Nq;

#pragma unroll 4
    for (int ii = 0; ii < 64; ii++) {
        int ad = adjp[(size_t)ii * Nq];
        float4 e4 = ep[(size_t)ii * Nq];
        float v0 = ssi[0][ii] + e4.x*ae[0][0] + e4.y*ae[0][1] + e4.z*ae[0][2] + e4.w*ae[0][3];
        float v1 = ssi[1][ii] + e4.x*ae[1][0] + e4.y*ae[1][1] + e4.z*ae[1][2] + e4.w*ae[1][3];
        float v2 = ssi[2][ii] + e4.x*ae[2][0] + e4.y*ae[2][1] + e4.z*ae[2][2] + e4.w*ae[2][3];
        float v3 = ssi[3][ii] + e4.x*ae[3][0] + e4.y*ae[3][1] + e4.z*ae[3][2] + e4.w*ae[3][3];
        float w0 = (ad > 0) ? tf32r(__expf(v0)) : 0.f;
        float w1 = (ad > 0) ? tf32r(__expf(v1)) : 0.f;
        float w2 = (ad > 0) ? tf32r(__expf(v2)) : 0.f;
        float w3 = (ad > 0) ? tf32r(__expf(v3)) : 0.f;
        size_t ro = (size_t)ii * Nq;
        wp[ro]             = w0;
        wp[ro + hstride]   = w1;
        wp[ro + 2*hstride] = w2;
        wp[ro + 3*hstride] = w3;
        acc0 += w0; acc1 += w1; acc2 += w2; acc3 += w3;
    }
    int base = ((ic * Bq + b) * Hq) * Nq + j;
    g_lp[base + 0 * Nq] = acc0;
    g_lp[base + 1 * Nq] = acc1;
    g_lp[base + 2 * Nq] = acc2;
    g_lp[base + 3 * Nq] = acc3;
}

// ------- k3: l reduction, htT[bh][d][j] = tf32(ht[j][d]/l[j]) -------
__global__ __launch_bounds__(256)
void k3_scale_T() {
    int bh = blockIdx.y;
    int j0 = blockIdx.x * 256;
    int t = threadIdx.x;
    __shared__ float sm[256][33];
    __shared__ float sinv[256];
    int b = bh >> 2, h = bh & 3;
    float l = 0.f;
#pragma unroll
    for (int ic = 0; ic < NIC; ic++) l += g_lp[((ic * Bq + b) * Hq + h) * Nq + j0 + t];
    sinv[t] = (l > 0.f) ? 1.f / l : 0.f;

    const float4* hp = (const float4*)(g_ht + ((size_t)bh * Nq + j0) * HIDq);
    for (int q = t; q < 256 * HIDq / 4; q += 256) {
        float4 v = hp[q];
        int r = q >> 3, d0 = (q & 7) * 4;
        sm[r][d0] = v.x; sm[r][d0+1] = v.y; sm[r][d0+2] = v.z; sm[r][d0+3] = v.w;
    }
    __syncthreads();
    for (int q = t; q < HIDq * 256; q += 256) {
        int d = q >> 8, r = q & 255;
        g_htT[((size_t)bh * HIDq + d) * Nq + j0 + r] = tf32r(sm[r][d] * sinv[r]);
    }
}

// ---------------- k4: mma.sync tf32 GEMM  out = w @ htp ----------------
__global__ __launch_bounds__(128)
void k4_mma(float* __restrict__ out) {
    extern __shared__ __align__(16) float dsm[];
    const uint32_t sbase = s2u(dsm);

    int t = threadIdx.x;
    int w = t >> 5, lane = t & 31;
    int bh = blockIdx.y;
    int i0 = blockIdx.x * 128;
    int b = bh >> 2, h = bh & 3;

    // gmem source pointers (per-thread staging geometry)
    const float* aSrc = g_w   + ((size_t)bh * Nq + i0 + t) * Nq;            // A row t
    int brow = t >> 2, bs0 = (t & 3) * 2;
    const float* bSrc = g_htT + ((size_t)bh * HIDq + brow) * Nq;            // B row t>>2

    // fragment geometry
    int gro = lane >> 2;      // group (row/col-of-n)
    int tig = lane & 3;       // thread-in-group (col/k)

    float acc[2][4][4];
#pragma unroll
    for (int mt = 0; mt < 2; mt++)
#pragma unroll
        for (int nt = 0; nt < 4; nt++)
#pragma unroll
            for (int q = 0; q < 4; q++) acc[mt][nt][q] = 0.f;

#define LOAD_CHUNK(c, s) do {                                                   \
        const float* as_ = aSrc + (c) * KC;                                     \
        const float* bs_ = bSrc + (c) * KC;                                     \
        uint32_t aB = sbase + ((s) * STAGE_F + t * RS) * 4;                     \
        uint32_t bB = sbase + ((s) * STAGE_F + A_STAGE_F + brow * RS) * 4;      \
        _Pragma("unroll")                                                       \
        for (int sg = 0; sg < 8; sg++) cpa16(aB + sg * 16, as_ + sg * 4);       \
        _Pragma("unroll")                                                       \
        for (int e = 0; e < 2; e++)                                             \
            cpa16(bB + (bs0 + e) * 16, bs_ + (bs0 + e) * 4);                    \
        asm volatile("cp.async.commit_group;" ::: "memory");                    \
    } while (0)

#pragma unroll
    for (int s = 0; s < STAGES; s++) LOAD_CHUNK(s, s);

    for (int c = 0; c < NCHUNK; c++) {
        int s = c & (STAGES - 1);
        asm volatile("cp.async.wait_group %0;" :: "n"(STAGES - 1) : "memory");
        __syncthreads();

        const float* sA = dsm + s * STAGE_F;
        const float* sB = dsm + s * STAGE_F + A_STAGE_F;

#pragma unroll
        for (int ks = 0; ks < 4; ks++) {
            int kb = ks * 8;
            uint32_t aF[2][4];
#pragma unroll
            for (int mt = 0; mt < 2; mt++) {
                const float* ap = sA + (w * 32 + mt * 16 + gro) * RS + kb + tig;
                aF[mt][0] = __float_as_uint(ap[0]);
                aF[mt][1] = __float_as_uint(ap[8 * RS]);
                aF[mt][2] = __float_as_uint(ap[4]);
                aF[mt][3] = __float_as_uint(ap[8 * RS + 4]);
            }
            uint32_t bF[4][2];
#pragma unroll
            for (int nt = 0; nt < 4; nt++) {
                const float* bp = sB + (nt * 8 + gro) * RS + kb + tig;
                bF[nt][0] = __float_as_uint(bp[0]);
                bF[nt][1] = __float_as_uint(bp[4]);
            }
#pragma unroll
            for (int mt = 0; mt < 2; mt++)
#pragma unroll
                for (int nt = 0; nt < 4; nt++) {
                    asm volatile(
                        "mma.sync.aligned.m16n8k8.row.col.f32.tf32.tf32.f32 "
                        "{%0,%1,%2,%3}, {%4,%5,%6,%7}, {%8,%9}, {%0,%1,%2,%3};"
                        : "+f"(acc[mt][nt][0]), "+f"(acc[mt][nt][1]),
                          "+f"(acc[mt][nt][2]), "+f"(acc[mt][nt][3])
                        : "r"(aF[mt][0]), "r"(aF[mt][1]), "r"(aF[mt][2]), "r"(aF[mt][3]),
                          "r"(bF[nt][0]), "r"(bF[nt][1]));
                }
        }
        __syncthreads();
        if (c + STAGES < NCHUNK) LOAD_CHUNK(c + STAGES, s);
    }

    // epilogue: D frag rows gro(+8), cols 2*tig(+1) per (mt, nt) tile
#pragma unroll
    for (int mt = 0; mt < 2; mt++) {
        int r0 = i0 + w * 32 + mt * 16 + gro;
#pragma unroll
        for (int nt = 0; nt < 4; nt++) {
            int col = h * HIDq + nt * 8 + 2 * tig;
            float* o0 = out + ((size_t)(b * Nq + r0)) * (Hq * HIDq) + col;
            float* o1 = out + ((size_t)(b * Nq + r0 + 8)) * (Hq * HIDq) + col;
            o0[0] = acc[mt][nt][0]; o0[1] = acc[mt][nt][1];
            o1[0] = acc[mt][nt][2]; o1[1] = acc[mt][nt][3];
        }
    }
}

extern "C" void kernel_launch(void* const* d_in, const int* in_sizes, int n_in,
                              void* d_out, int out_size) {
    const float* hin  = (const float*)d_in[0];
    const int*   adj  = (const int*)  d_in[1];
    const float* edge = (const float*)d_in[2];
    const float* W    = (const float*)d_in[3];
    const float* a    = (const float*)d_in[4];
    float* out = (float*)d_out;

    cudaFuncSetAttribute(k4_mma, cudaFuncAttributeMaxDynamicSharedMemorySize, SMEM_DYN);

    k1_proj<<<Bq * Nq, 128>>>(hin, W, a);
    k2_w<<<dim3(NIC, Nq / 256, Bq), 256>>>(adj, (const float4*)edge, a);
    k3_scale_T<<<dim3(Nq / 256, Bq * Hq), 256>>>();
    k4_mma<<<dim3(Nq / 128, Bq * Hq), 128, SMEM_DYN>>>(out);
}

// round 7
// speedup vs baseline: 5.9607x; 1.4575x over previous
#include <cuda_runtime.h>
#include <cuda_fp16.h>
#include <cstdint>

#define Bq 4
#define Nq 2048
#define FIN 128
#define Hq 4
#define HIDq 32
#define NIC 32
#define KC 64
#define NCHUNK (Nq/KC)     // 32
#define STAGES 4
#define HT_SCALE 32768.0f          // 2^15, exact
#define HT_INV   (1.0f/32768.0f)

#define RSH 72                       // halves per padded row (conflict-free frags)
#define A_ROWS 64
#define A_STAGE_H (A_ROWS*RSH)       // 4608 halves
#define B_STAGE_H (32*RSH)           // 2304 halves
#define STAGE_H   (A_STAGE_H + B_STAGE_H)
#define SMEM_DYN  (STAGES * STAGE_H * 2 + 16)

// Scratch (device globals: no allocations allowed)
__device__ float  g_ht[Bq*Hq*Nq*HIDq];           // [bh][n][d]
__device__ float  g_si[Bq*Hq*Nq];                // [bh][n]
__device__ float  g_lp[NIC*Bq*Hq*Nq];            // partial column sums
__device__ __half g_w[(size_t)Bq*Hq*Nq*Nq];      // fp16 weights [bh][i][j]
__device__ __half g_htT[Bq*Hq*HIDq*Nq];          // fp16 (htp^T * 2^15) [bh][d][j]

__device__ __forceinline__ uint32_t s2u(const void* p) {
    uint32_t a;
    asm("{ .reg .u64 t; cvta.to.shared.u64 t, %1; cvt.u32.u64 %0, t; }" : "=r"(a) : "l"(p));
    return a;
}
__device__ __forceinline__ void cpa16(uint32_t dst, const void* src) {
    asm volatile("cp.async.cg.shared.global [%0], [%1], 16;" :: "r"(dst), "l"(src) : "memory");
}

// ---------------- k1: ht = h @ W, s_i = <ht, a_i> ----------------
__global__ void k1_proj(const float* __restrict__ hin,
                        const float* __restrict__ W,
                        const float* __restrict__ a) {
    int bn = blockIdx.x;
    int b = bn >> 11, n = bn & (Nq - 1);
    __shared__ float sh[FIN];
    int t = threadIdx.x;
    sh[t] = hin[bn * FIN + t];
    __syncthreads();
    float acc = 0.f;
#pragma unroll 16
    for (int k = 0; k < FIN; k++) acc += sh[k] * W[(k << 7) + t];
    int hh = t >> 5, d = t & 31;
    g_ht[(((b * Hq + hh) * Nq) + n) * HIDq + d] = acc;
    float v = acc * a[hh * 68 + d];
#pragma unroll
    for (int o = 16; o > 0; o >>= 1) v += __shfl_xor_sync(0xffffffffu, v, o);
    if (d == 0) g_si[(b * Hq + hh) * Nq + n] = v;
}

// ------- k2: w = fp16(mask * exp(s_i + s_e)), partial column sums -------
__global__ __launch_bounds__(256)
void k2_w(const int* __restrict__ adj,
          const float4* __restrict__ edge,
          const float* __restrict__ a) {
    int t  = threadIdx.x;
    int j  = blockIdx.y * 256 + t;
    int b  = blockIdx.z;
    int ic = blockIdx.x;
    int i0 = ic * 64;

    __shared__ float ssi[Hq][64];
    {
        int hh = t >> 6, il = t & 63;
        ssi[hh][il] = g_si[(b * Hq + hh) * Nq + i0 + il];
    }
    float ae[4][4];
#pragma unroll
    for (int hh = 0; hh < 4; hh++)
#pragma unroll
        for (int e = 0; e < 4; e++) ae[hh][e] = a[hh * 68 + 2 * HIDq + e];
    __syncthreads();

    float acc0 = 0.f, acc1 = 0.f, acc2 = 0.f, acc3 = 0.f;
    const int*    adjp = adj  + (size_t)(b * Nq + i0) * Nq + j;
    const float4* ep   = edge + (size_t)(b * Nq + i0) * Nq + j;
    __half* wp = g_w + (size_t)(b * Hq * Nq + i0) * Nq + j;
    const size_t hstride = (size_t)Nq * Nq;

#pragma unroll 4
    for (int ii = 0; ii < 64; ii++) {
        int ad = adjp[(size_t)ii * Nq];
        float4 e4 = ep[(size_t)ii * Nq];
        float v0 = ssi[0][ii] + e4.x*ae[0][0] + e4.y*ae[0][1] + e4.z*ae[0][2] + e4.w*ae[0][3];
        float v1 = ssi[1][ii] + e4.x*ae[1][0] + e4.y*ae[1][1] + e4.z*ae[1][2] + e4.w*ae[1][3];
        float v2 = ssi[2][ii] + e4.x*ae[2][0] + e4.y*ae[2][1] + e4.z*ae[2][2] + e4.w*ae[2][3];
        float v3 = ssi[3][ii] + e4.x*ae[3][0] + e4.y*ae[3][1] + e4.z*ae[3][2] + e4.w*ae[3][3];
        __half w0 = (ad > 0) ? __float2half_rn(fminf(__expf(v0), 60000.f)) : __half(0.f);
        __half w1 = (ad > 0) ? __float2half_rn(fminf(__expf(v1), 60000.f)) : __half(0.f);
        __half w2 = (ad > 0) ? __float2half_rn(fminf(__expf(v2), 60000.f)) : __half(0.f);
        __half w3 = (ad > 0) ? __float2half_rn(fminf(__expf(v3), 60000.f)) : __half(0.f);
        size_t ro = (size_t)ii * Nq;
        wp[ro]             = w0;
        wp[ro + hstride]   = w1;
        wp[ro + 2*hstride] = w2;
        wp[ro + 3*hstride] = w3;
        acc0 += __half2float(w0); acc1 += __half2float(w1);
        acc2 += __half2float(w2); acc3 += __half2float(w3);
    }
    int base = ((ic * Bq + b) * Hq) * Nq + j;
    g_lp[base + 0 * Nq] = acc0;
    g_lp[base + 1 * Nq] = acc1;
    g_lp[base + 2 * Nq] = acc2;
    g_lp[base + 3 * Nq] = acc3;
}

// ------- k3: l reduction, htT[bh][d][j] = fp16(ht[j][d]/l[j] * 2^15) -------
__global__ __launch_bounds__(256)
void k3_scale_T() {
    int bh = blockIdx.y;
    int j0 = blockIdx.x * 256;
    int t = threadIdx.x;
    __shared__ float sm[256][33];
    __shared__ float sinv[256];
    int b = bh >> 2, h = bh & 3;
    float l = 0.f;
#pragma unroll
    for (int ic = 0; ic < NIC; ic++) l += g_lp[((ic * Bq + b) * Hq + h) * Nq + j0 + t];
    sinv[t] = (l > 0.f) ? HT_SCALE / l : 0.f;

    const float4* hp = (const float4*)(g_ht + ((size_t)bh * Nq + j0) * HIDq);
    for (int q = t; q < 256 * HIDq / 4; q += 256) {
        float4 v = hp[q];
        int r = q >> 3, d0 = (q & 7) * 4;
        sm[r][d0] = v.x; sm[r][d0+1] = v.y; sm[r][d0+2] = v.z; sm[r][d0+3] = v.w;
    }
    __syncthreads();
    for (int q = t; q < HIDq * 256; q += 256) {
        int d = q >> 8, r = q & 255;
        g_htT[((size_t)bh * HIDq + d) * Nq + j0 + r] = __float2half_rn(sm[r][d] * sinv[r]);
    }
}

// ---------------- k4: mma.sync fp16 GEMM  out = (w @ htp_scaled) * 2^-15 ----------------
__global__ __launch_bounds__(128)
void k4_mma(float* __restrict__ out) {
    extern __shared__ __align__(16) __half hsm[];
    const uint32_t sbase = s2u(hsm);

    int t = threadIdx.x;
    int w = t >> 5, lane = t & 31;
    int bh = blockIdx.y;
    int i0 = blockIdx.x * 64;
    int b = bh >> 2, h = bh & 3;

    // staging geometry
    int arow = t >> 1, aseg0 = (t & 1) * 4;     // 64 rows, 2 thr/row, 4 segs each
    int brow = t >> 2, bseg0 = (t & 3) * 2;     // 32 rows, 4 thr/row, 2 segs each
    const __half* aSrc = g_w   + ((size_t)bh * Nq + i0 + arow) * Nq;
    const __half* bSrc = g_htT + ((size_t)bh * HIDq + brow) * Nq;

    // fragment geometry
    int gro = lane >> 2;      // group row / n-col
    int tig = lane & 3;       // thread-in-group

    float acc[4][4];
#pragma unroll
    for (int nt = 0; nt < 4; nt++)
#pragma unroll
        for (int q = 0; q < 4; q++) acc[nt][q] = 0.f;

#define LOAD_CHUNK(c, s) do {                                                      \
        const __half* as_ = aSrc + (c) * KC;                                       \
        const __half* bs_ = bSrc + (c) * KC;                                       \
        uint32_t aB = sbase + ((s) * STAGE_H + arow * RSH) * 2;                    \
        uint32_t bB = sbase + ((s) * STAGE_H + A_STAGE_H + brow * RSH) * 2;        \
        _Pragma("unroll")                                                          \
        for (int sg = 0; sg < 4; sg++)                                             \
            cpa16(aB + (aseg0 + sg) * 16, as_ + (aseg0 + sg) * 8);                 \
        _Pragma("unroll")                                                          \
        for (int e = 0; e < 2; e++)                                                \
            cpa16(bB + (bseg0 + e) * 16, bs_ + (bseg0 + e) * 8);                   \
        asm volatile("cp.async.commit_group;" ::: "memory");                       \
    } while (0)

#pragma unroll
    for (int s = 0; s < STAGES; s++) LOAD_CHUNK(s, s);

    for (int c = 0; c < NCHUNK; c++) {
        int s = c & (STAGES - 1);
        asm volatile("cp.async.wait_group %0;" :: "n"(STAGES - 1) : "memory");
        __syncthreads();

        const __half* sA = hsm + s * STAGE_H;
        const __half* sB = hsm + s * STAGE_H + A_STAGE_H;

#pragma unroll
        for (int ks = 0; ks < 4; ks++) {
            int kb = ks * 16;
            const __half* ap = sA + (w * 16 + gro) * RSH + kb + 2 * tig;
            uint32_t a0 = *(const uint32_t*)(ap);
            uint32_t a1 = *(const uint32_t*)(ap + 8 * RSH);
            uint32_t a2 = *(const uint32_t*)(ap + 8);
            uint32_t a3 = *(const uint32_t*)(ap + 8 * RSH + 8);
#pragma unroll
            for (int nt = 0; nt < 4; nt++) {
                const __half* bp = sB + (nt * 8 + gro) * RSH + kb + 2 * tig;
                uint32_t b0 = *(const uint32_t*)(bp);
                uint32_t b1 = *(const uint32_t*)(bp + 8);
                asm volatile(
                    "mma.sync.aligned.m16n8k16.row.col.f32.f16.f16.f32 "
                    "{%0,%1,%2,%3}, {%4,%5,%6,%7}, {%8,%9}, {%0,%1,%2,%3};"
                    : "+f"(acc[nt][0]), "+f"(acc[nt][1]),
                      "+f"(acc[nt][2]), "+f"(acc[nt][3])
                    : "r"(a0), "r"(a1), "r"(a2), "r"(a3), "r"(b0), "r"(b1));
            }
        }
        __syncthreads();
        if (c + STAGES < NCHUNK) LOAD_CHUNK(c + STAGES, s);
    }

    // epilogue: rows gro / gro+8 of warp tile, cols 2*tig(+1) per n-tile; undo 2^15
    int r0 = i0 + w * 16 + gro;
#pragma unroll
    for (int nt = 0; nt < 4; nt++) {
        int col = h * HIDq + nt * 8 + 2 * tig;
        float2 v0 = {acc[nt][0] * HT_INV, acc[nt][1] * HT_INV};
        float2 v1 = {acc[nt][2] * HT_INV, acc[nt][3] * HT_INV};
        *(float2*)(out + ((size_t)(b * Nq + r0))     * (Hq * HIDq) + col) = v0;
        *(float2*)(out + ((size_t)(b * Nq + r0 + 8)) * (Hq * HIDq) + col) = v1;
    }
}

extern "C" void kernel_launch(void* const* d_in, const int* in_sizes, int n_in,
                              void* d_out, int out_size) {
    const float* hin  = (const float*)d_in[0];
    const int*   adj  = (const int*)  d_in[1];
    const float* edge = (const float*)d_in[2];
    const float* W    = (const float*)d_in[3];
    const float* a    = (const float*)d_in[4];
    float* out = (float*)d_out;

    cudaFuncSetAttribute(k4_mma, cudaFuncAttributeMaxDynamicSharedMemorySize, SMEM_DYN);

    k1_proj<<<Bq * Nq, 128>>>(hin, W, a);
    k2_w<<<dim3(NIC, Nq / 256, Bq), 256>>>(adj, (const float4*)edge, a);
    k3_scale_T<<<dim3(Nq / 256, Bq * Hq), 256>>>();
    k4_mma<<<dim3(Nq / 64, Bq * Hq), 128, SMEM_DYN>>>(out);
}